// round 2
// baseline (speedup 1.0000x reference)
#include <cuda_runtime.h>
#include <cuda_fp16.h>

namespace {
constexpr int B   = 64;
constexpr int S   = 512;
constexpr int H   = 1024;
constexpr int L   = 2;
constexpr int G4  = 4 * H;        // 4096
constexpr int BH  = B * H;        // 65536
constexpr int BSH = B * S * H;    // 33554432
constexpr int NB  = 64;           // persistent blocks (<= SM count, all co-resident)
constexpr int SMEM_PERSIST = 64 * (H + 8) * 2 + 64 * 72 * 2;  // Wh slice + h staging
}

// ---- device scratch (static, no allocations) ----
__device__ __half g_seqA[BSH];            // layer input, fp16
__device__ __half g_seqB[BSH];            // layer-0 output, fp16
__device__ float  g_gx[S * B * G4];       // precomputed input projections, fp32
__device__ __half g_wip[L * G4 * H];      // permuted+transposed Wi [l][n'][k]
__device__ __half g_whp[L * G4 * H];      // permuted+transposed Wh [l][n'][k]
__device__ float  g_bip[L * G4];
__device__ float  g_bhp[L * G4];
__device__ __half g_h[2 * BH];            // double-buffered hidden state, fp16
__device__ unsigned g_flag[NB];           // per-block progress counters

// ---- m16n8k16 fp16 MMA, fp32 accumulate ----
__device__ __forceinline__ void mma16816(float* d, const unsigned* a, const unsigned* b) {
    asm volatile(
        "mma.sync.aligned.m16n8k16.row.col.f32.f16.f16.f32 "
        "{%0,%1,%2,%3}, {%4,%5,%6,%7}, {%8,%9}, {%0,%1,%2,%3};\n"
        : "+f"(d[0]), "+f"(d[1]), "+f"(d[2]), "+f"(d[3])
        : "r"(a[0]), "r"(a[1]), "r"(a[2]), "r"(a[3]), "r"(b[0]), "r"(b[1]));
}

__device__ __forceinline__ unsigned ld_acq(const unsigned* p) {
    unsigned v;
    asm volatile("ld.global.acquire.gpu.u32 %0, [%1];" : "=r"(v) : "l"(p) : "memory");
    return v;
}
__device__ __forceinline__ void st_rel(unsigned* p, unsigned v) {
    asm volatile("st.global.release.gpu.u32 [%0], %1;" :: "l"(p), "r"(v) : "memory");
}

// ---- x (fp32) -> seqA (fp16) ----
__global__ void k_convert_x(const float4* __restrict__ x) {
    int i = blockIdx.x * blockDim.x + threadIdx.x;
    if (i < BSH / 4) {
        float4 v = x[i];
        __half2* o = reinterpret_cast<__half2*>(g_seqA);
        o[2 * i]     = __floats2half2_rn(v.x, v.y);
        o[2 * i + 1] = __floats2half2_rn(v.z, v.w);
    }
}

// ---- weights: [L,4,H(k),H(h)] fp32 -> permuted n-major fp16 [l][n'][k] ----
// n' = (h/8)*32 + g*8 + (h%8)
__global__ void k_convert_w(const float* __restrict__ Wi, const float* __restrict__ bi,
                            const float* __restrict__ Wh, const float* __restrict__ bh) {
    int stride = gridDim.x * blockDim.x;
    int tid0 = blockIdx.x * blockDim.x + threadIdx.x;
    const int total = L * G4 * H;
    for (int idx = tid0; idx < total; idx += stride) {
        int l   = idx / (G4 * H);
        int rem = idx - l * (G4 * H);
        int np  = rem / H;
        int k   = rem - np * H;
        int jb = np >> 5, g = (np >> 3) & 3, jr = np & 7;
        int h = jb * 8 + jr;
        int src = ((l * 4 + g) * H + k) * H + h;
        g_wip[idx] = __float2half(Wi[src]);
        g_whp[idx] = __float2half(Wh[src]);
    }
    for (int idx = tid0; idx < L * G4; idx += stride) {
        int l  = idx / G4;
        int np = idx - l * G4;
        int jb = np >> 5, g = (np >> 3) & 3, jr = np & 7;
        int h = jb * 8 + jr;
        g_bip[idx] = bi[(l * 4 + g) * H + h];
        g_bhp[idx] = bh[(l * 4 + g) * H + h];
    }
}

// ---- zero h buffer 0 + flags (before each layer's persistent kernel) ----
__global__ void k_init() {
    int i = blockIdx.x * blockDim.x + threadIdx.x;
    if (i < BH) g_h[i] = __float2half(0.f);
    if (i < NB) g_flag[i] = 0;
}

// ---- input projection GEMM: gx[s][b][n'] = seq[b*S+s][:] @ Wp[n'][:] + bip[n'] ----
// M=32768, N=4096, K=1024.  Block tile 128x128xK32, 8 warps (warp tile 32x64).
__global__ __launch_bounds__(256) void k_gemm_in(int layer) {
    __shared__ __half As[128][40];
    __shared__ __half Bs[128][40];
    const __half* __restrict__ Aseq = (layer == 0) ? g_seqA : g_seqB;
    const __half* __restrict__ Wp   = g_wip + layer * (G4 * H);
    const float*  __restrict__ bip  = g_bip + layer * G4;

    int tid = threadIdx.x, lane = tid & 31, warp = tid >> 5;
    int wm = warp & 3, wn = warp >> 2;
    int bm = blockIdx.y, bn = blockIdx.x;
    const __half* Ab = Aseq + (long long)bm * 128 * H;
    const __half* Bb = Wp   + (long long)bn * 128 * H;

    float acc[2][8][4];
#pragma unroll
    for (int mt = 0; mt < 2; mt++)
#pragma unroll
        for (int nt = 0; nt < 8; nt++)
#pragma unroll
            for (int i = 0; i < 4; i++) acc[mt][nt][i] = 0.f;

    for (int kt = 0; kt < H; kt += 32) {
#pragma unroll
        for (int i = 0; i < 2; i++) {
            int idx = i * 256 + tid;
            int r = idx >> 2, c8 = (idx & 3) << 3;
            *(uint4*)&As[r][c8] = *(const uint4*)&Ab[r * H + kt + c8];
            *(uint4*)&Bs[r][c8] = *(const uint4*)&Bb[r * H + kt + c8];
        }
        __syncthreads();
#pragma unroll
        for (int kk = 0; kk < 2; kk++) {
            unsigned a[2][4], b[8][2];
#pragma unroll
            for (int mt = 0; mt < 2; mt++)
#pragma unroll
                for (int i = 0; i < 4; i++) {
                    int r = wm * 32 + mt * 16 + (lane >> 2) + 8 * (i & 1);
                    int c = kk * 16 + (lane & 3) * 2 + 8 * (i >> 1);
                    a[mt][i] = *(const unsigned*)&As[r][c];
                }
#pragma unroll
            for (int nt = 0; nt < 8; nt++)
#pragma unroll
                for (int i = 0; i < 2; i++) {
                    int n = wn * 64 + nt * 8 + (lane >> 2);
                    int c = kk * 16 + (lane & 3) * 2 + 8 * i;
                    b[nt][i] = *(const unsigned*)&Bs[n][c];
                }
#pragma unroll
            for (int mt = 0; mt < 2; mt++)
#pragma unroll
                for (int nt = 0; nt < 8; nt++)
                    mma16816(acc[mt][nt], a[mt], b[nt]);
        }
        __syncthreads();
    }
#pragma unroll
    for (int mt = 0; mt < 2; mt++)
#pragma unroll
        for (int nt = 0; nt < 8; nt++)
#pragma unroll
            for (int i2 = 0; i2 < 2; i2++) {
                int gr = bm * 128 + wm * 32 + mt * 16 + (lane >> 2) + 8 * i2;
                int gc = bn * 128 + wn * 64 + nt * 8 + (lane & 3) * 2;
                int s  = gr & (S - 1);
                int bb = gr >> 9;   // S = 512
                float2 bv = *(const float2*)&bip[gc];
                float2 v;
                v.x = acc[mt][nt][2 * i2]     + bv.x;
                v.y = acc[mt][nt][2 * i2 + 1] + bv.y;
                *(float2*)&g_gx[(s * B + bb) * G4 + gc] = v;
            }
}

// ---- persistent recurrence: all 512 steps of one layer in a single kernel ----
// 64 blocks x 256 threads.  Block jb owns 64 n'-cols (= 16 h-cols x 4 gates),
// Wh slice (128 KB) held in smem for the whole kernel; c held in registers.
// Warp (wm = warp&3, wj = warp>>2): m16 x n32 tile; the 4 n-tiles of a warp are
// the 4 gates of the same 8 h-cols -> all gates of an output land in one lane.
__global__ __launch_bounds__(256) void k_persist(int layer, float* __restrict__ out) {
    extern __shared__ __half sm[];
    __half (*Whs)[H + 8] = reinterpret_cast<__half(*)[H + 8]>(sm);
    __half (*As)[72]     = reinterpret_cast<__half(*)[72]>(sm + 64 * (H + 8));

    int jb = blockIdx.x, tid = threadIdx.x, lane = tid & 31, warp = tid >> 5;
    int wm = warp & 3, wj = warp >> 2;

    // Load this block's Wh slice into smem once (64 rows x 1024 k, fp16).
    const __half* __restrict__ Wb = g_whp + (size_t)layer * G4 * H + (size_t)jb * 64 * H;
    for (int idx = tid; idx < 64 * (H / 8); idx += 256) {
        int r  = idx >> 7;           // H/8 = 128 chunks per row
        int c8 = (idx & 127) << 3;
        *(uint4*)&Whs[r][c8] = *(const uint4*)&Wb[r * H + c8];
    }

    // Per-lane recurrent-bias values (4 gates x 2 cols).
    const float* __restrict__ bhr = g_bhp + layer * G4 + jb * 64 + wj * 32;
    float2 bh_g[4];
#pragma unroll
    for (int g = 0; g < 4; g++) bh_g[g] = *(const float2*)&bhr[g * 8 + (lane & 3) * 2];

    float creg[2][2] = {{0.f, 0.f}, {0.f, 0.f}};   // cell state lives in registers

    __syncthreads();

    for (int t = 0; t < S; t++) {
        const __half* __restrict__ hin = g_h + (t & 1) * BH;
        __half* __restrict__ hout      = g_h + ((t + 1) & 1) * BH;

        // Wait until every block has finished step t-1 (h_t fully published).
        if (warp == 0) {
            unsigned tgt = (unsigned)t;
            for (;;) {
                unsigned a = ld_acq(&g_flag[lane]);
                unsigned b = ld_acq(&g_flag[lane + 32]);
                if (__all_sync(0xffffffffu, a >= tgt && b >= tgt)) break;
            }
        }
        __syncthreads();

        float acc[4][4];
#pragma unroll
        for (int nt = 0; nt < 4; nt++)
#pragma unroll
            for (int i = 0; i < 4; i++) acc[nt][i] = 0.f;

        for (int kt = 0; kt < H; kt += 64) {
#pragma unroll
            for (int i = 0; i < 2; i++) {
                int idx = i * 256 + tid;
                int r = idx >> 3, c8 = (idx & 7) << 3;
                *(uint4*)&As[r][c8] = *(const uint4*)&hin[r * H + kt + c8];
            }
            __syncthreads();
#pragma unroll
            for (int kk = 0; kk < 4; kk++) {
                unsigned a[4];
#pragma unroll
                for (int i = 0; i < 4; i++) {
                    int r = wm * 16 + (lane >> 2) + 8 * (i & 1);
                    int c = kk * 16 + (lane & 3) * 2 + 8 * (i >> 1);
                    a[i] = *(const unsigned*)&As[r][c];
                }
#pragma unroll
                for (int nt = 0; nt < 4; nt++) {
                    unsigned b2[2];
                    int n = wj * 32 + nt * 8 + (lane >> 2);
#pragma unroll
                    for (int i = 0; i < 2; i++) {
                        int c = kt + kk * 16 + (lane & 3) * 2 + 8 * i;
                        b2[i] = *(const unsigned*)&Whs[n][c];
                    }
                    mma16816(acc[nt], a, b2);
                }
            }
            __syncthreads();
        }

        // Elementwise LSTM update; all 4 gates of an output are in this lane.
#pragma unroll
        for (int i2 = 0; i2 < 2; i2++) {
            int r = wm * 16 + (lane >> 2) + 8 * i2;    // batch index
            const float* __restrict__ gxr =
                g_gx + ((size_t)t * B + r) * G4 + jb * 64 + wj * 32;
            float2 gxv[4];
#pragma unroll
            for (int g = 0; g < 4; g++) gxv[g] = *(const float2*)&gxr[g * 8 + (lane & 3) * 2];

            float hv2[2], cn2[2];
#pragma unroll
            for (int bs = 0; bs < 2; bs++) {
                int ai = 2 * i2 + bs;
                float pi = acc[0][ai] + (bs ? gxv[0].y : gxv[0].x) + (bs ? bh_g[0].y : bh_g[0].x);
                float pf = acc[1][ai] + (bs ? gxv[1].y : gxv[1].x) + (bs ? bh_g[1].y : bh_g[1].x);
                float pg = acc[2][ai] + (bs ? gxv[2].y : gxv[2].x) + (bs ? bh_g[2].y : bh_g[2].x);
                float po = acc[3][ai] + (bs ? gxv[3].y : gxv[3].x) + (bs ? bh_g[3].y : bh_g[3].x);
                float ig = 1.f / (1.f + __expf(-pi));
                float fg = 1.f / (1.f + __expf(-pf));
                float gg = tanhf(pg);
                float og = 1.f / (1.f + __expf(-po));
                float cn = fg * creg[i2][bs] + ig * gg;
                creg[i2][bs] = cn;
                cn2[bs] = cn;
                hv2[bs] = og * tanhf(cn);
            }
            int jbase = jb * 16 + wj * 8 + (lane & 3) * 2;
            *(__half2*)&hout[r * H + jbase] = __floats2half2_rn(hv2[0], hv2[1]);
            if (layer == 0)
                *(__half2*)&g_seqB[((size_t)r * S + t) * H + jbase] =
                    __floats2half2_rn(hv2[0], hv2[1]);
            if (t == S - 1) {
#pragma unroll
                for (int bs = 0; bs < 2; bs++) {
                    int j = jbase + bs;
                    out[BH + layer * BH + r * H + j]          = hv2[bs];   // h_n[l]
                    out[BH + L * BH + layer * BH + r * H + j] = cn2[bs];   // c_n[l]
                    if (layer == L - 1) out[r * H + j] = hv2[bs];          // seq[:, -1, :]
                }
            }
        }

        // Publish h_{t+1}: fence all our global writes, then release our flag.
        __threadfence();
        __syncthreads();
        if (tid == 0) st_rel(&g_flag[jb], (unsigned)(t + 1));
    }
}

extern "C" void kernel_launch(void* const* d_in, const int* in_sizes, int n_in,
                              void* d_out, int out_size) {
    (void)in_sizes; (void)n_in; (void)out_size;
    const float* x  = (const float*)d_in[0];
    const float* Wi = (const float*)d_in[1];
    const float* bi = (const float*)d_in[2];
    const float* Wh = (const float*)d_in[3];
    const float* bh = (const float*)d_in[4];
    float* out = (float*)d_out;

    cudaFuncSetAttribute(k_persist, cudaFuncAttributeMaxDynamicSharedMemorySize,
                         SMEM_PERSIST);

    k_convert_x<<<(BSH / 4 + 255) / 256, 256>>>((const float4*)x);
    k_convert_w<<<2048, 256>>>(Wi, bi, Wh, bh);

    for (int l = 0; l < L; l++) {
        dim3 grid(G4 / 128, (B * S) / 128);   // (32, 256)
        k_gemm_in<<<grid, 256>>>(l);
        k_init<<<(BH + 255) / 256, 256>>>();
        k_persist<<<NB, 256, SMEM_PERSIST>>>(l, out);
    }
}

// round 3
// speedup vs baseline: 1.4872x; 1.4872x over previous
#include <cuda_runtime.h>
#include <cuda_fp16.h>

namespace {
constexpr int B   = 64;
constexpr int S   = 512;
constexpr int H   = 1024;
constexpr int L   = 2;
constexpr int G4  = 4 * H;        // 4096
constexpr int BH  = B * H;        // 65536
constexpr int BSH = B * S * H;    // 33554432
constexpr int NB  = 64;           // persistent blocks
constexpr int WH_LD = H + 8;      // 1032, padded Wh smem row
// persistent smem: Wh slice + 3-stage h staging
constexpr int SMEM_PERSIST = 64 * WH_LD * 2 + 3 * 64 * 72 * 2;   // 159744
// gemm smem: 3 stages x (A 128x40 + B 128x40) halves
constexpr int SMEM_GEMM = 3 * 2 * 128 * 40 * 2;                  // 61440
}

// ---- device scratch (static, no allocations) ----
__device__ __half g_seqA[BSH];            // layer-0 input (x, fp16), row = b*S+s
__device__ __half g_seqB[BSH];            // layer-0 output (fp16), row = s*B+b (time-major)
__device__ float  g_gx[S * B * G4];       // input projections, fp32, [(s*B+b)][n']
__device__ __half g_wip[L * G4 * H];      // permuted+transposed Wi [l][n'][k]
__device__ __half g_whp[L * G4 * H];      // permuted+transposed Wh [l][n'][k]
__device__ float  g_bip[L * G4];
__device__ float  g_bhp[L * G4];
__device__ __half g_h[2 * BH];            // double-buffered hidden state, fp16
__device__ unsigned g_flag[NB];           // per-block progress counters

// ---- primitives ----
__device__ __forceinline__ void mma16816(float* d, const unsigned* a, const unsigned* b) {
    asm volatile(
        "mma.sync.aligned.m16n8k16.row.col.f32.f16.f16.f32 "
        "{%0,%1,%2,%3}, {%4,%5,%6,%7}, {%8,%9}, {%0,%1,%2,%3};\n"
        : "+f"(d[0]), "+f"(d[1]), "+f"(d[2]), "+f"(d[3])
        : "r"(a[0]), "r"(a[1]), "r"(a[2]), "r"(a[3]), "r"(b[0]), "r"(b[1]));
}
__device__ __forceinline__ void ldm_x4(unsigned* r, unsigned saddr) {
    asm volatile("ldmatrix.sync.aligned.m8n8.x4.shared.b16 {%0,%1,%2,%3}, [%4];"
                 : "=r"(r[0]), "=r"(r[1]), "=r"(r[2]), "=r"(r[3]) : "r"(saddr));
}
__device__ __forceinline__ void cpa16(void* s, const void* g) {
    unsigned sa = (unsigned)__cvta_generic_to_shared(s);
    asm volatile("cp.async.cg.shared.global [%0], [%1], 16;" :: "r"(sa), "l"(g));
}
__device__ __forceinline__ void cp_commit() { asm volatile("cp.async.commit_group;"); }
template <int N> __device__ __forceinline__ void cp_wait() {
    asm volatile("cp.async.wait_group %0;" :: "n"(N));
}
__device__ __forceinline__ unsigned ld_acq(const unsigned* p) {
    unsigned v;
    asm volatile("ld.global.acquire.gpu.u32 %0, [%1];" : "=r"(v) : "l"(p) : "memory");
    return v;
}
__device__ __forceinline__ void st_rel(unsigned* p, unsigned v) {
    asm volatile("st.global.release.gpu.u32 [%0], %1;" :: "l"(p), "r"(v) : "memory");
}

// ---- x (fp32) -> seqA (fp16) ----
__global__ void k_convert_x(const float4* __restrict__ x) {
    int i = blockIdx.x * blockDim.x + threadIdx.x;
    if (i < BSH / 4) {
        float4 v = x[i];
        __half2* o = reinterpret_cast<__half2*>(g_seqA);
        o[2 * i]     = __floats2half2_rn(v.x, v.y);
        o[2 * i + 1] = __floats2half2_rn(v.z, v.w);
    }
}

// ---- weight transpose via smem tiles: coalesced read AND write ----
// n' = (h/8)*32 + g*8 + (h%8)
__global__ __launch_bounds__(256) void k_transpose_w(const float* __restrict__ Wi,
                                                     const float* __restrict__ Wh) {
    __shared__ __half ti[32][33], th[32][33];
    int bid = blockIdx.x;
    int ht = bid & 31; bid >>= 5;
    int kt = bid & 31; bid >>= 5;
    int g  = bid & 3;
    int l  = bid >> 2;
    int tid = threadIdx.x, c = tid & 31, r0 = tid >> 5;
    const float* si = Wi + (((size_t)(l * 4 + g) * H + kt * 32) * H) + ht * 32;
    const float* sh = Wh + (((size_t)(l * 4 + g) * H + kt * 32) * H) + ht * 32;
#pragma unroll
    for (int rr = 0; rr < 32; rr += 8) {
        int k = rr + r0;
        ti[k][c] = __float2half(si[(size_t)k * H + c]);
        th[k][c] = __float2half(sh[(size_t)k * H + c]);
    }
    __syncthreads();
#pragma unroll
    for (int rr = 0; rr < 32; rr += 8) {
        int hr = rr + r0;
        int h  = ht * 32 + hr;
        int np = (h >> 3) * 32 + g * 8 + (h & 7);
        size_t dst = (size_t)l * G4 * H + (size_t)np * H + kt * 32 + c;
        g_wip[dst] = ti[c][hr];
        g_whp[dst] = th[c][hr];
    }
}

__global__ void k_bias(const float* __restrict__ bi, const float* __restrict__ bh) {
    int idx = blockIdx.x * blockDim.x + threadIdx.x;
    if (idx < L * G4) {
        int l = idx / G4, np = idx % G4;
        int jb = np >> 5, g = (np >> 3) & 3, jr = np & 7;
        int h = jb * 8 + jr;
        g_bip[idx] = bi[(l * 4 + g) * H + h];
        g_bhp[idx] = bh[(l * 4 + g) * H + h];
    }
}

__global__ void k_init() {
    int i = blockIdx.x * blockDim.x + threadIdx.x;
    if (i < BH) g_h[i] = __float2half(0.f);
    if (i < NB) g_flag[i] = 0;
}

// ---- input projection GEMM, 3-stage cp.async pipeline ----
// gx[row'][n'] = A[row][:] @ Wp[n'][:] + bip[n'].  M=32768, N=4096, K=1024.
// layer0: A = g_seqA (row = b*S+s), out row' = s*B+b.  layer1: A = g_seqB (row = s*B+b), out row' = row.
__global__ __launch_bounds__(256) void k_gemm_in(int layer) {
    extern __shared__ __half dsm[];
    const __half* __restrict__ Aseq = (layer == 0) ? g_seqA : g_seqB;
    const __half* __restrict__ Wp   = g_wip + (size_t)layer * G4 * H;
    const float*  __restrict__ bip  = g_bip + layer * G4;

    int tid = threadIdx.x, lane = tid & 31, warp = tid >> 5;
    int wm = warp & 3, wn = warp >> 2;
    int bm = blockIdx.y, bn = blockIdx.x;
    const __half* Ab = Aseq + (size_t)bm * 128 * H;
    const __half* Bb = Wp   + (size_t)bn * 128 * H;

    auto AsS = [&](int s) { return reinterpret_cast<__half(*)[40]>(dsm + s * 2 * 128 * 40); };
    auto BsS = [&](int s) { return reinterpret_cast<__half(*)[40]>(dsm + s * 2 * 128 * 40 + 128 * 40); };

    auto load_stage = [&](int kti, int s) {
        int kt = kti * 32;
        __half(*As)[40] = AsS(s);
        __half(*Bs)[40] = BsS(s);
#pragma unroll
        for (int i = 0; i < 2; i++) {
            int idx = i * 256 + tid;
            int r = idx >> 2, c8 = (idx & 3) << 3;
            cpa16(&As[r][c8], &Ab[(size_t)r * H + kt + c8]);
            cpa16(&Bs[r][c8], &Bb[(size_t)r * H + kt + c8]);
        }
        cp_commit();
    };

    float acc[2][8][4];
#pragma unroll
    for (int mt = 0; mt < 2; mt++)
#pragma unroll
        for (int nt = 0; nt < 8; nt++)
#pragma unroll
            for (int i = 0; i < 4; i++) acc[mt][nt][i] = 0.f;

    load_stage(0, 0);
    load_stage(1, 1);

    for (int kti = 0; kti < 32; kti++) {
        cp_wait<1>();
        __syncthreads();
        if (kti + 2 < 32) load_stage(kti + 2, (kti + 2) % 3);
        else cp_commit();
        __half(*As)[40] = AsS(kti % 3);
        __half(*Bs)[40] = BsS(kti % 3);
#pragma unroll
        for (int kk = 0; kk < 2; kk++) {
            unsigned a[2][4], b[8][2];
#pragma unroll
            for (int mt = 0; mt < 2; mt++)
#pragma unroll
                for (int i = 0; i < 4; i++) {
                    int r = wm * 32 + mt * 16 + (lane >> 2) + 8 * (i & 1);
                    int c = kk * 16 + (lane & 3) * 2 + 8 * (i >> 1);
                    a[mt][i] = *(const unsigned*)&As[r][c];
                }
#pragma unroll
            for (int nt = 0; nt < 8; nt++)
#pragma unroll
                for (int i = 0; i < 2; i++) {
                    int n = wn * 64 + nt * 8 + (lane >> 2);
                    int c = kk * 16 + (lane & 3) * 2 + 8 * i;
                    b[nt][i] = *(const unsigned*)&Bs[n][c];
                }
#pragma unroll
            for (int mt = 0; mt < 2; mt++)
#pragma unroll
                for (int nt = 0; nt < 8; nt++)
                    mma16816(acc[mt][nt], a[mt], b[nt]);
        }
    }

#pragma unroll
    for (int mt = 0; mt < 2; mt++)
#pragma unroll
        for (int nt = 0; nt < 8; nt++)
#pragma unroll
            for (int i2 = 0; i2 < 2; i2++) {
                int gr = bm * 128 + wm * 32 + mt * 16 + (lane >> 2) + 8 * i2;
                int gc = bn * 128 + wn * 64 + nt * 8 + (lane & 3) * 2;
                int orow = (layer == 0) ? ((gr & (S - 1)) * B + (gr >> 9)) : gr;
                float2 bv = *(const float2*)&bip[gc];
                float2 v;
                v.x = acc[mt][nt][2 * i2]     + bv.x;
                v.y = acc[mt][nt][2 * i2 + 1] + bv.y;
                *(float2*)&g_gx[(size_t)orow * G4 + gc] = v;
            }
}

// ---- persistent recurrence: pipelined + ldmatrix ----
// 64 blocks x 256 threads.  Block jb owns 64 n'-cols (16 h-cols x 4 gates).
// Warp (wm, wj): m16 x n32 tile; acc[g] = gate g of the same 8 h-cols.
__global__ __launch_bounds__(256) void k_persist(int layer, float* __restrict__ out) {
    extern __shared__ __half sm[];
    __half (*Whs)[WH_LD] = reinterpret_cast<__half(*)[WH_LD]>(sm);
    __half* As_base = sm + 64 * WH_LD;    // 3 stages of [64][72]

    int jb = blockIdx.x, tid = threadIdx.x, lane = tid & 31, warp = tid >> 5;
    int wm = warp & 3, wj = warp >> 2;

    const __half* __restrict__ Wb = g_whp + (size_t)layer * G4 * H + (size_t)jb * 64 * H;
    for (int idx = tid; idx < 64 * 128; idx += 256) {
        int r = idx >> 7, c8 = (idx & 127) << 3;
        *(uint4*)&Whs[r][c8] = *(const uint4*)&Wb[(size_t)r * H + c8];
    }

    const float* __restrict__ bhr = g_bhp + layer * G4 + jb * 64 + wj * 32;
    float2 bh_g[4];
#pragma unroll
    for (int g = 0; g < 4; g++) bh_g[g] = *(const float2*)&bhr[g * 8 + (lane & 3) * 2];

    float creg[2][2] = {{0.f, 0.f}, {0.f, 0.f}};

    unsigned whs_s = (unsigned)__cvta_generic_to_shared(&Whs[0][0]);
    unsigned as_s  = (unsigned)__cvta_generic_to_shared(As_base);

    // ldmatrix per-lane address components (canonical fragment layouts)
    int a_row   = wm * 16 + (lane & 15);
    int a_coloff = (lane >> 4) * 8;
    int b_n     = wj * 32 + (lane & 7) + ((lane >> 4) & 1) * 8;
    int b_koff  = ((lane >> 3) & 1) * 8;
    unsigned baddr0 = whs_s + (unsigned)(b_n * WH_LD + b_koff) * 2;

    __syncthreads();

    for (int t = 0; t < S; t++) {
        const __half* __restrict__ hin = g_h + (t & 1) * BH;
        __half* __restrict__ hout      = g_h + ((t + 1) & 1) * BH;

        if (warp == 0) {
            unsigned tgt = (unsigned)t;
            for (;;) {
                unsigned a = ld_acq(&g_flag[lane]);
                unsigned b = ld_acq(&g_flag[lane + 32]);
                if (__all_sync(0xffffffffu, a >= tgt && b >= tgt)) break;
            }
        }
        __syncthreads();

        // prefetch gx for this step into registers (DRAM latency hides under GEMM)
        float2 gxp[2][4];
#pragma unroll
        for (int i2 = 0; i2 < 2; i2++) {
            int r = wm * 16 + (lane >> 2) + 8 * i2;
            const float* gxr = g_gx + ((size_t)t * B + r) * G4 + jb * 64 + wj * 32;
#pragma unroll
            for (int g = 0; g < 4; g++)
                gxp[i2][g] = *(const float2*)&gxr[g * 8 + (lane & 3) * 2];
        }

        auto load_st = [&](int kti, int s) {
            int kt = kti * 64;
            __half* base = As_base + s * 64 * 72;
#pragma unroll
            for (int i = 0; i < 2; i++) {
                int idx = i * 256 + tid;
                int r = idx >> 3, c8 = (idx & 7) << 3;
                cpa16(base + r * 72 + c8, &hin[(size_t)r * H + kt + c8]);
            }
            cp_commit();
        };
        load_st(0, 0);
        load_st(1, 1);

        float acc[4][4];
#pragma unroll
        for (int nt = 0; nt < 4; nt++)
#pragma unroll
            for (int i = 0; i < 4; i++) acc[nt][i] = 0.f;

        for (int kti = 0; kti < 16; kti++) {
            cp_wait<1>();
            __syncthreads();
            if (kti + 2 < 16) load_st(kti + 2, (kti + 2) % 3);
            else cp_commit();
            unsigned as_stage = as_s + (unsigned)((kti % 3) * 64 * 72) * 2;
            int kt = kti * 64;
#pragma unroll
            for (int kk = 0; kk < 4; kk++) {
                unsigned a[4], bq0[4], bq1[4];
                ldm_x4(a, as_stage + (unsigned)(a_row * 72 + kk * 16 + a_coloff) * 2);
                unsigned bcol = (unsigned)(kt + kk * 16) * 2;
                ldm_x4(bq0, baddr0 + bcol);                           // gates 0,1
                ldm_x4(bq1, baddr0 + (unsigned)(16 * WH_LD) * 2 + bcol); // gates 2,3
                mma16816(acc[0], a, &bq0[0]);
                mma16816(acc[1], a, &bq0[2]);
                mma16816(acc[2], a, &bq1[0]);
                mma16816(acc[3], a, &bq1[2]);
            }
        }

        // elementwise LSTM update; all 4 gates of an output are in this lane
#pragma unroll
        for (int i2 = 0; i2 < 2; i2++) {
            int r = wm * 16 + (lane >> 2) + 8 * i2;    // batch index
            float hv2[2], cn2[2];
#pragma unroll
            for (int bs = 0; bs < 2; bs++) {
                int ai = 2 * i2 + bs;
                float pi = acc[0][ai] + (bs ? gxp[i2][0].y : gxp[i2][0].x) + (bs ? bh_g[0].y : bh_g[0].x);
                float pf = acc[1][ai] + (bs ? gxp[i2][1].y : gxp[i2][1].x) + (bs ? bh_g[1].y : bh_g[1].x);
                float pg = acc[2][ai] + (bs ? gxp[i2][2].y : gxp[i2][2].x) + (bs ? bh_g[2].y : bh_g[2].x);
                float po = acc[3][ai] + (bs ? gxp[i2][3].y : gxp[i2][3].x) + (bs ? bh_g[3].y : bh_g[3].x);
                float ig = 1.f / (1.f + __expf(-pi));
                float fg = 1.f / (1.f + __expf(-pf));
                float gg = tanhf(pg);
                float og = 1.f / (1.f + __expf(-po));
                float cn = fg * creg[i2][bs] + ig * gg;
                creg[i2][bs] = cn;
                cn2[bs] = cn;
                hv2[bs] = og * tanhf(cn);
            }
            int jbase = jb * 16 + wj * 8 + (lane & 3) * 2;
            *(__half2*)&hout[r * H + jbase] = __floats2half2_rn(hv2[0], hv2[1]);
            if (layer == 0)   // time-major: coalesced
                *(__half2*)&g_seqB[((size_t)t * B + r) * H + jbase] =
                    __floats2half2_rn(hv2[0], hv2[1]);
            if (t == S - 1) {
#pragma unroll
                for (int bs = 0; bs < 2; bs++) {
                    int j = jbase + bs;
                    out[BH + layer * BH + r * H + j]          = hv2[bs];   // h_n[l]
                    out[BH + L * BH + layer * BH + r * H + j] = cn2[bs];   // c_n[l]
                    if (layer == L - 1) out[r * H + j] = hv2[bs];          // seq[:, -1, :]
                }
            }
        }

        __threadfence();
        __syncthreads();
        if (tid == 0) st_rel(&g_flag[jb], (unsigned)(t + 1));
    }
}

extern "C" void kernel_launch(void* const* d_in, const int* in_sizes, int n_in,
                              void* d_out, int out_size) {
    (void)in_sizes; (void)n_in; (void)out_size;
    const float* x  = (const float*)d_in[0];
    const float* Wi = (const float*)d_in[1];
    const float* bi = (const float*)d_in[2];
    const float* Wh = (const float*)d_in[3];
    const float* bh = (const float*)d_in[4];
    float* out = (float*)d_out;

    cudaFuncSetAttribute(k_persist, cudaFuncAttributeMaxDynamicSharedMemorySize, SMEM_PERSIST);
    cudaFuncSetAttribute(k_gemm_in, cudaFuncAttributeMaxDynamicSharedMemorySize, SMEM_GEMM);

    k_convert_x<<<(BSH / 4 + 255) / 256, 256>>>((const float4*)x);
    k_transpose_w<<<L * 4 * 32 * 32, 256>>>(Wi, Wh);
    k_bias<<<(L * G4 + 255) / 256, 256>>>(bi, bh);

    for (int l = 0; l < L; l++) {
        dim3 grid(G4 / 128, (B * S) / 128);   // (32, 256)
        k_gemm_in<<<grid, 256, SMEM_GEMM>>>(l);
        k_init<<<(BH + 255) / 256, 256>>>();
        k_persist<<<NB, 256, SMEM_PERSIST>>>(l, out);
    }
}

// round 5
// speedup vs baseline: 1.6153x; 1.0862x over previous
#include <cuda_runtime.h>
#include <cuda_fp16.h>

namespace {
constexpr int B   = 64;
constexpr int S   = 512;
constexpr int H   = 1024;
constexpr int L   = 2;
constexpr int G4  = 4 * H;        // 4096
constexpr int BH  = B * H;        // 65536
constexpr int BSH = B * S * H;    // 33554432
constexpr int NBP = 128;          // persistent blocks (<= SM count, co-resident)
constexpr int WH_LD = H + 8;      // 1032, padded Wh smem row
// persistent smem: Wh slice (64 rows) + 3-stage h staging (32x72)
constexpr int SMEM_PERSIST = 64 * WH_LD * 2 + 3 * 32 * 72 * 2;   // 145920
// gemm smem: 3 stages x (A 128x40 + B 128x40) halves
constexpr int SMEM_GEMM = 3 * 2 * 128 * 40 * 2;                  // 61440
}

// ---- device scratch (static, no allocations) ----
__device__ __half g_seqA[BSH];            // layer-0 input (x, fp16), row = b*S+s
__device__ __half g_seqB[BSH];            // layer-0 output (fp16), row = s*B+b (time-major)
__device__ float  g_gx[S * B * G4];       // input projections, fp32, [(s*B+b)][n']
__device__ __half g_wip[L * G4 * H];      // permuted+transposed Wi [l][n'][k]
__device__ __half g_whp[L * G4 * H];      // permuted+transposed Wh [l][n'][k]
__device__ float  g_bip[L * G4];
__device__ float  g_bhp[L * G4];
__device__ __half g_h[2 * BH];            // double-buffered hidden state, fp16
__device__ unsigned g_flag[NBP];          // per-block progress counters

// ---- primitives ----
__device__ __forceinline__ void mma16816(float* d, const unsigned* a, const unsigned* b) {
    asm volatile(
        "mma.sync.aligned.m16n8k16.row.col.f32.f16.f16.f32 "
        "{%0,%1,%2,%3}, {%4,%5,%6,%7}, {%8,%9}, {%0,%1,%2,%3};\n"
        : "+f"(d[0]), "+f"(d[1]), "+f"(d[2]), "+f"(d[3])
        : "r"(a[0]), "r"(a[1]), "r"(a[2]), "r"(a[3]), "r"(b[0]), "r"(b[1]));
}
__device__ __forceinline__ void ldm_x4(unsigned* r, unsigned saddr) {
    asm volatile("ldmatrix.sync.aligned.m8n8.x4.shared.b16 {%0,%1,%2,%3}, [%4];"
                 : "=r"(r[0]), "=r"(r[1]), "=r"(r[2]), "=r"(r[3]) : "r"(saddr));
}
__device__ __forceinline__ void cpa16(void* s, const void* g) {
    unsigned sa = (unsigned)__cvta_generic_to_shared(s);
    asm volatile("cp.async.cg.shared.global [%0], [%1], 16;" :: "r"(sa), "l"(g));
}
__device__ __forceinline__ void cp_commit() { asm volatile("cp.async.commit_group;"); }
template <int N> __device__ __forceinline__ void cp_wait() {
    asm volatile("cp.async.wait_group %0;" :: "n"(N));
}
__device__ __forceinline__ unsigned ld_acq(const unsigned* p) {
    unsigned v;
    asm volatile("ld.global.acquire.gpu.u32 %0, [%1];" : "=r"(v) : "l"(p) : "memory");
    return v;
}
__device__ __forceinline__ void st_rel(unsigned* p, unsigned v) {
    asm volatile("st.global.release.gpu.u32 [%0], %1;" :: "l"(p), "r"(v) : "memory");
}

// ---- x (fp32) -> seqA (fp16) ----
__global__ void k_convert_x(const float4* __restrict__ x) {
    int i = blockIdx.x * blockDim.x + threadIdx.x;
    if (i < BSH / 4) {
        float4 v = x[i];
        __half2* o = reinterpret_cast<__half2*>(g_seqA);
        o[2 * i]     = __floats2half2_rn(v.x, v.y);
        o[2 * i + 1] = __floats2half2_rn(v.z, v.w);
    }
}

// ---- weight transpose via smem tiles ----
// n' = (h/8)*32 + g*8 + (h%8)
__global__ __launch_bounds__(256) void k_transpose_w(const float* __restrict__ Wi,
                                                     const float* __restrict__ Wh) {
    __shared__ __half ti[32][33], th[32][33];
    int bid = blockIdx.x;
    int ht = bid & 31; bid >>= 5;
    int kt = bid & 31; bid >>= 5;
    int g  = bid & 3;
    int l  = bid >> 2;
    int tid = threadIdx.x, c = tid & 31, r0 = tid >> 5;
    const float* si = Wi + (((size_t)(l * 4 + g) * H + kt * 32) * H) + ht * 32;
    const float* sh = Wh + (((size_t)(l * 4 + g) * H + kt * 32) * H) + ht * 32;
#pragma unroll
    for (int rr = 0; rr < 32; rr += 8) {
        int k = rr + r0;
        ti[k][c] = __float2half(si[(size_t)k * H + c]);
        th[k][c] = __float2half(sh[(size_t)k * H + c]);
    }
    __syncthreads();
#pragma unroll
    for (int rr = 0; rr < 32; rr += 8) {
        int hr = rr + r0;
        int h  = ht * 32 + hr;
        int np = (h >> 3) * 32 + g * 8 + (h & 7);
        size_t dst = (size_t)l * G4 * H + (size_t)np * H + kt * 32 + c;
        g_wip[dst] = ti[c][hr];
        g_whp[dst] = th[c][hr];
    }
}

__global__ void k_bias(const float* __restrict__ bi, const float* __restrict__ bh) {
    int idx = blockIdx.x * blockDim.x + threadIdx.x;
    if (idx < L * G4) {
        int l = idx / G4, np = idx % G4;
        int jb = np >> 5, g = (np >> 3) & 3, jr = np & 7;
        int h = jb * 8 + jr;
        g_bip[idx] = bi[(l * 4 + g) * H + h];
        g_bhp[idx] = bh[(l * 4 + g) * H + h];
    }
}

__global__ void k_init() {
    int i = blockIdx.x * blockDim.x + threadIdx.x;
    if (i < BH) g_h[i] = __float2half(0.f);
    if (i < NBP) g_flag[i] = 0;
}

// ---- input projection GEMM, 3-stage cp.async pipeline + ldmatrix ----
// gx[row'][n'] = A[row][:] @ Wp[n'][:] + bip[n'].  M=32768, N=4096, K=1024.
__global__ __launch_bounds__(256) void k_gemm_in(int layer) {
    extern __shared__ __half dsm[];
    const __half* __restrict__ Aseq = (layer == 0) ? g_seqA : g_seqB;
    const __half* __restrict__ Wp   = g_wip + (size_t)layer * G4 * H;
    const float*  __restrict__ bip  = g_bip + layer * G4;

    int tid = threadIdx.x, lane = tid & 31, warp = tid >> 5;
    int wm = warp & 3, wn = warp >> 2;
    int bm = blockIdx.y, bn = blockIdx.x;
    const __half* Ab = Aseq + (size_t)bm * 128 * H;
    const __half* Bb = Wp   + (size_t)bn * 128 * H;

    unsigned sm_u = (unsigned)__cvta_generic_to_shared(dsm);

    auto load_stage = [&](int kti, int s) {
        int kt = kti * 32;
        __half* As = dsm + s * 2 * 128 * 40;
        __half* Bs = As + 128 * 40;
#pragma unroll
        for (int i = 0; i < 2; i++) {
            int idx = i * 256 + tid;
            int r = idx >> 2, c8 = (idx & 3) << 3;
            cpa16(As + r * 40 + c8, &Ab[(size_t)r * H + kt + c8]);
            cpa16(Bs + r * 40 + c8, &Bb[(size_t)r * H + kt + c8]);
        }
        cp_commit();
    };

    float acc[2][8][4];
#pragma unroll
    for (int mt = 0; mt < 2; mt++)
#pragma unroll
        for (int nt = 0; nt < 8; nt++)
#pragma unroll
            for (int i = 0; i < 4; i++) acc[mt][nt][i] = 0.f;

    // ldmatrix per-lane address components (validated fragment layouts)
    int a_row    = wm * 32 + (lane & 15);
    int a_coloff = (lane >> 4) * 8;
    int b_row    = wn * 64 + (lane & 7) + ((lane >> 4) & 1) * 8;
    int b_koff   = ((lane >> 3) & 1) * 8;

    load_stage(0, 0);
    load_stage(1, 1);

    for (int kti = 0; kti < 32; kti++) {
        cp_wait<1>();
        __syncthreads();
        if (kti + 2 < 32) load_stage(kti + 2, (kti + 2) % 3);
        else cp_commit();
        unsigned stA = sm_u + (unsigned)((kti % 3) * 2 * 128 * 40) * 2;
        unsigned stB = stA + (unsigned)(128 * 40) * 2;
#pragma unroll
        for (int kk = 0; kk < 2; kk++) {
            unsigned a[2][4], bq[4][4];
            unsigned acol = (unsigned)(kk * 16 + a_coloff) * 2;
            ldm_x4(a[0], stA + (unsigned)(a_row * 40) * 2 + acol);
            ldm_x4(a[1], stA + (unsigned)((a_row + 16) * 40) * 2 + acol);
            unsigned bcol = (unsigned)(kk * 16 + b_koff) * 2;
#pragma unroll
            for (int p = 0; p < 4; p++)
                ldm_x4(bq[p], stB + (unsigned)((b_row + p * 16) * 40) * 2 + bcol);
#pragma unroll
            for (int mt = 0; mt < 2; mt++)
#pragma unroll
                for (int nt = 0; nt < 8; nt++)
                    mma16816(acc[mt][nt], a[mt], &bq[nt >> 1][(nt & 1) * 2]);
        }
    }

#pragma unroll
    for (int mt = 0; mt < 2; mt++)
#pragma unroll
        for (int nt = 0; nt < 8; nt++)
#pragma unroll
            for (int i2 = 0; i2 < 2; i2++) {
                int gr = bm * 128 + wm * 32 + mt * 16 + (lane >> 2) + 8 * i2;
                int gc = bn * 128 + wn * 64 + nt * 8 + (lane & 3) * 2;
                int orow = (layer == 0) ? ((gr & (S - 1)) * B + (gr >> 9)) : gr;
                float2 bv = *(const float2*)&bip[gc];
                float2 v;
                v.x = acc[mt][nt][2 * i2]     + bv.x;
                v.y = acc[mt][nt][2 * i2 + 1] + bv.y;
                *(float2*)&g_gx[(size_t)orow * G4 + gc] = v;
            }
}

// ---- persistent recurrence: 128 blocks x 128 threads ----
// Block bx: jb = bx>>1 owns 64 n'-cols (16 h-cols x 4 gates); mh = bx&1 owns a
// 32-row batch half.  4 warps: wm = warp&1 (16-row half), wj = warp>>1 (32 n').
// Warp tile m16 x n32; all 4 gates of an output land in one lane.
__global__ __launch_bounds__(128) void k_persist(int layer, float* __restrict__ out) {
    extern __shared__ __half sm[];
    __half (*Whs)[WH_LD] = reinterpret_cast<__half(*)[WH_LD]>(sm);
    __half* As_base = sm + 64 * WH_LD;    // 3 stages of [32][72]

    int bx = blockIdx.x;
    int jb = bx >> 1, mh = bx & 1;
    int tid = threadIdx.x, lane = tid & 31, warp = tid >> 5;
    int wm = warp & 1, wj = warp >> 1;

    const __half* __restrict__ Wb = g_whp + (size_t)layer * G4 * H + (size_t)jb * 64 * H;
    for (int idx = tid; idx < 64 * 128; idx += 128) {
        int r = idx >> 7, c8 = (idx & 127) << 3;
        *(uint4*)&Whs[r][c8] = *(const uint4*)&Wb[(size_t)r * H + c8];
    }

    const float* __restrict__ bhr = g_bhp + layer * G4 + jb * 64 + wj * 32;
    float2 bh_g[4];
#pragma unroll
    for (int g = 0; g < 4; g++) bh_g[g] = *(const float2*)&bhr[g * 8 + (lane & 3) * 2];

    float creg[2][2] = {{0.f, 0.f}, {0.f, 0.f}};

    unsigned whs_s = (unsigned)__cvta_generic_to_shared(&Whs[0][0]);
    unsigned as_s  = (unsigned)__cvta_generic_to_shared(As_base);

    int a_row    = wm * 16 + (lane & 15);
    int a_coloff = (lane >> 4) * 8;
    int b_n      = wj * 32 + (lane & 7) + ((lane >> 4) & 1) * 8;
    int b_koff   = ((lane >> 3) & 1) * 8;
    unsigned baddr0 = whs_s + (unsigned)(b_n * WH_LD + b_koff) * 2;

    __syncthreads();

    for (int t = 0; t < S; t++) {
        const __half* __restrict__ hin = g_h + (t & 1) * BH;
        __half* __restrict__ hout      = g_h + ((t + 1) & 1) * BH;

        if (warp == 0) {
            unsigned tgt = (unsigned)t;
            for (;;) {
                unsigned a = ld_acq(&g_flag[lane]);
                unsigned b = ld_acq(&g_flag[lane + 32]);
                unsigned c = ld_acq(&g_flag[lane + 64]);
                unsigned d = ld_acq(&g_flag[lane + 96]);
                if (__all_sync(0xffffffffu,
                               a >= tgt && b >= tgt && c >= tgt && d >= tgt)) break;
            }
        }
        __syncthreads();

        // prefetch gx for this step (DRAM latency hides under the GEMM)
        float2 gxp[2][4];
#pragma unroll
        for (int i2 = 0; i2 < 2; i2++) {
            int r = mh * 32 + wm * 16 + (lane >> 2) + 8 * i2;
            const float* gxr = g_gx + ((size_t)t * B + r) * G4 + jb * 64 + wj * 32;
#pragma unroll
            for (int g = 0; g < 4; g++)
                gxp[i2][g] = *(const float2*)&gxr[g * 8 + (lane & 3) * 2];
        }

        auto load_st = [&](int kti, int s) {
            int kt = kti * 64;
            __half* base = As_base + s * 32 * 72;
#pragma unroll
            for (int i = 0; i < 2; i++) {
                int idx = i * 128 + tid;
                int r = idx >> 3, c8 = (idx & 7) << 3;
                cpa16(base + r * 72 + c8, &hin[(size_t)(mh * 32 + r) * H + kt + c8]);
            }
            cp_commit();
        };
        load_st(0, 0);
        load_st(1, 1);

        float acc[4][4];
#pragma unroll
        for (int nt = 0; nt < 4; nt++)
#pragma unroll
            for (int i = 0; i < 4; i++) acc[nt][i] = 0.f;

        for (int kti = 0; kti < 16; kti++) {
            cp_wait<1>();
            __syncthreads();
            if (kti + 2 < 16) load_st(kti + 2, (kti + 2) % 3);
            else cp_commit();
            unsigned as_stage = as_s + (unsigned)((kti % 3) * 32 * 72) * 2;
            int kt = kti * 64;
#pragma unroll
            for (int kk = 0; kk < 4; kk++) {
                unsigned a[4], bq0[4], bq1[4];
                ldm_x4(a, as_stage + (unsigned)(a_row * 72 + kk * 16 + a_coloff) * 2);
                unsigned bcol = (unsigned)(kt + kk * 16) * 2;
                ldm_x4(bq0, baddr0 + bcol);                              // gates 0,1
                ldm_x4(bq1, baddr0 + (unsigned)(16 * WH_LD) * 2 + bcol); // gates 2,3
                mma16816(acc[0], a, &bq0[0]);
                mma16816(acc[1], a, &bq0[2]);
                mma16816(acc[2], a, &bq1[0]);
                mma16816(acc[3], a, &bq1[2]);
            }
        }

        // elementwise LSTM update; all 4 gates of an output are in this lane
#pragma unroll
        for (int i2 = 0; i2 < 2; i2++) {
            int r = mh * 32 + wm * 16 + (lane >> 2) + 8 * i2;    // batch index
            float hv2[2], cn2[2];
#pragma unroll
            for (int bs = 0; bs < 2; bs++) {
                int ai = 2 * i2 + bs;
                float pi = acc[0][ai] + (bs ? gxp[i2][0].y : gxp[i2][0].x) + (bs ? bh_g[0].y : bh_g[0].x);
                float pf = acc[1][ai] + (bs ? gxp[i2][1].y : gxp[i2][1].x) + (bs ? bh_g[1].y : bh_g[1].x);
                float pg = acc[2][ai] + (bs ? gxp[i2][2].y : gxp[i2][2].x) + (bs ? bh_g[2].y : bh_g[2].x);
                float po = acc[3][ai] + (bs ? gxp[i2][3].y : gxp[i2][3].x) + (bs ? bh_g[3].y : bh_g[3].x);
                float ig = 1.f / (1.f + __expf(-pi));
                float fg = 1.f / (1.f + __expf(-pf));
                float gg = tanhf(pg);
                float og = 1.f / (1.f + __expf(-po));
                float cn = fg * creg[i2][bs] + ig * gg;
                creg[i2][bs] = cn;
                cn2[bs] = cn;
                hv2[bs] = og * tanhf(cn);
            }
            int jbase = jb * 16 + wj * 8 + (lane & 3) * 2;
            *(__half2*)&hout[r * H + jbase] = __floats2half2_rn(hv2[0], hv2[1]);
            if (layer == 0)   // time-major: coalesced
                *(__half2*)&g_seqB[((size_t)t * B + r) * H + jbase] =
                    __floats2half2_rn(hv2[0], hv2[1]);
            if (t == S - 1) {
#pragma unroll
                for (int bs = 0; bs < 2; bs++) {
                    int j = jbase + bs;
                    out[BH + layer * BH + r * H + j]          = hv2[bs];   // h_n[l]
                    out[BH + L * BH + layer * BH + r * H + j] = cn2[bs];   // c_n[l]
                    if (layer == L - 1) out[r * H + j] = hv2[bs];          // seq[:, -1, :]
                }
            }
        }

        __threadfence();
        __syncthreads();
        if (tid == 0) st_rel(&g_flag[bx], (unsigned)(t + 1));
    }
}

extern "C" void kernel_launch(void* const* d_in, const int* in_sizes, int n_in,
                              void* d_out, int out_size) {
    (void)in_sizes; (void)n_in; (void)out_size;
    const float* x  = (const float*)d_in[0];
    const float* Wi = (const float*)d_in[1];
    const float* bi = (const float*)d_in[2];
    const float* Wh = (const float*)d_in[3];
    const float* bh = (const float*)d_in[4];
    float* out = (float*)d_out;

    cudaFuncSetAttribute(k_persist, cudaFuncAttributeMaxDynamicSharedMemorySize, SMEM_PERSIST);
    cudaFuncSetAttribute(k_gemm_in, cudaFuncAttributeMaxDynamicSharedMemorySize, SMEM_GEMM);

    k_convert_x<<<(BSH / 4 + 255) / 256, 256>>>((const float4*)x);
    k_transpose_w<<<L * 4 * 32 * 32, 256>>>(Wi, Wh);
    k_bias<<<(L * G4 + 255) / 256, 256>>>(bi, bh);

    for (int l = 0; l < L; l++) {
        dim3 grid(G4 / 128, (B * S) / 128);   // (32, 256)
        k_gemm_in<<<grid, 256, SMEM_GEMM>>>(l);
        k_init<<<(BH + 255) / 256, 256>>>();
        k_persist<<<NBP, 128, SMEM_PERSIST>>>(l, out);
    }
}

// round 8
// speedup vs baseline: 2.5311x; 1.5669x over previous
#include <cuda_runtime.h>
#include <cuda_fp16.h>

namespace {
constexpr int B   = 64;
constexpr int S   = 512;
constexpr int H   = 1024;
constexpr int L   = 2;
constexpr int G4  = 4 * H;        // 4096
constexpr int BH  = B * H;        // 65536
constexpr int BSH = B * S * H;    // 33554432
constexpr int NBP = 128;          // persistent blocks (co-resident)
constexpr int WH_LD = H + 8;      // 1032, padded Wh smem row
constexpr int BLOB = 32 * H * 2;  // 65536 B: one block's h slice
// persistent smem: Wh slice (64x1032 fp16) + h blob (64KB) + mbarrier
constexpr int SMEM_PERSIST = 64 * WH_LD * 2 + BLOB + 16;         // 197648
// gemm smem: 3 stages x (A 128x40 + B 128x40) halves
constexpr int SMEM_GEMM = 3 * 2 * 128 * 40 * 2;                  // 61440
}

// ---- device scratch (static, no allocations) ----
__device__ __half g_seqA[BSH];            // layer-0 input (x, fp16), row = b*S+s
__device__ __half g_seqB[BSH];            // layer-0 output (fp16), row = s*B+b
__device__ float  g_gx[S * B * G4];       // input projections, fp32, [(s*B+b)][n']
__device__ __half g_wip[L * G4 * H];      // permuted+transposed Wi [l][n'][k]
__device__ __half g_whp[L * G4 * H];      // permuted+transposed Wh [l][n'][k]
__device__ float  g_bip[L * G4];
__device__ float  g_bhp[L * G4];
__device__ __half g_h[2 * BH];            // double-buffered hidden, SWIZZLED blobs
__device__ unsigned g_ctr;                // global step counter (barrier)

// ---- primitives ----
__device__ __forceinline__ void mma16816(float* d, const unsigned* a, const unsigned* b) {
    asm volatile(
        "mma.sync.aligned.m16n8k16.row.col.f32.f16.f16.f32 "
        "{%0,%1,%2,%3}, {%4,%5,%6,%7}, {%8,%9}, {%0,%1,%2,%3};\n"
        : "+f"(d[0]), "+f"(d[1]), "+f"(d[2]), "+f"(d[3])
        : "r"(a[0]), "r"(a[1]), "r"(a[2]), "r"(a[3]), "r"(b[0]), "r"(b[1]));
}
__device__ __forceinline__ void ldm_x4(unsigned* r, unsigned saddr) {
    asm volatile("ldmatrix.sync.aligned.m8n8.x4.shared.b16 {%0,%1,%2,%3}, [%4];"
                 : "=r"(r[0]), "=r"(r[1]), "=r"(r[2]), "=r"(r[3]) : "r"(saddr));
}
__device__ __forceinline__ void cpa16(void* s, const void* g) {
    unsigned sa = (unsigned)__cvta_generic_to_shared(s);
    asm volatile("cp.async.cg.shared.global [%0], [%1], 16;" :: "r"(sa), "l"(g));
}
__device__ __forceinline__ void cp_commit() { asm volatile("cp.async.commit_group;"); }
template <int N> __device__ __forceinline__ void cp_wait() {
    asm volatile("cp.async.wait_group %0;" :: "n"(N));
}
__device__ __forceinline__ unsigned ld_acq(const unsigned* p) {
    unsigned v;
    asm volatile("ld.global.acquire.gpu.u32 %0, [%1];" : "=r"(v) : "l"(p) : "memory");
    return v;
}
__device__ __forceinline__ void atom_add_release(unsigned* p, unsigned v) {
    unsigned old;
    asm volatile("atom.global.add.release.gpu.u32 %0, [%1], %2;"
                 : "=r"(old) : "l"(p), "r"(v) : "memory");
}
__device__ __forceinline__ void mbar_init(unsigned mbar, unsigned cnt) {
    asm volatile("mbarrier.init.shared.b64 [%0], %1;" :: "r"(mbar), "r"(cnt) : "memory");
}
__device__ __forceinline__ void fence_proxy_async_cta() {
    asm volatile("fence.proxy.async.shared::cta;" ::: "memory");
}
__device__ __forceinline__ void mbar_expect_tx(unsigned mbar, unsigned bytes) {
    asm volatile("mbarrier.arrive.expect_tx.shared.b64 _, [%0], %1;"
                 :: "r"(mbar), "r"(bytes) : "memory");
}
__device__ __forceinline__ void bulk_g2s(unsigned sdst, const void* gsrc,
                                         unsigned bytes, unsigned mbar) {
    asm volatile(
        "cp.async.bulk.shared::cluster.global.mbarrier::complete_tx::bytes "
        "[%0], [%1], %2, [%3];"
        :: "r"(sdst), "l"(gsrc), "r"(bytes), "r"(mbar) : "memory");
}
__device__ __forceinline__ void mbar_wait(unsigned mbar, unsigned parity) {
    asm volatile(
        "{\n\t.reg .pred P;\n"
        "W%=:\n\t"
        "mbarrier.try_wait.parity.shared.b64 P, [%0], %1;\n\t"
        "@!P bra W%=;\n\t"
        "}\n"
        :: "r"(mbar), "r"(parity) : "memory");
}

// ---- x (fp32) -> seqA (fp16) ----
__global__ void k_convert_x(const float4* __restrict__ x) {
    int i = blockIdx.x * blockDim.x + threadIdx.x;
    if (i < BSH / 4) {
        float4 v = x[i];
        __half2* o = reinterpret_cast<__half2*>(g_seqA);
        o[2 * i]     = __floats2half2_rn(v.x, v.y);
        o[2 * i + 1] = __floats2half2_rn(v.z, v.w);
    }
}

// ---- weight transpose via smem tiles ----
// n' = (h/8)*32 + g*8 + (h%8)
__global__ __launch_bounds__(256) void k_transpose_w(const float* __restrict__ Wi,
                                                     const float* __restrict__ Wh) {
    __shared__ __half ti[32][33], th[32][33];
    int bid = blockIdx.x;
    int ht = bid & 31; bid >>= 5;
    int kt = bid & 31; bid >>= 5;
    int g  = bid & 3;
    int l  = bid >> 2;
    int tid = threadIdx.x, c = tid & 31, r0 = tid >> 5;
    const float* si = Wi + (((size_t)(l * 4 + g) * H + kt * 32) * H) + ht * 32;
    const float* sh = Wh + (((size_t)(l * 4 + g) * H + kt * 32) * H) + ht * 32;
#pragma unroll
    for (int rr = 0; rr < 32; rr += 8) {
        int k = rr + r0;
        ti[k][c] = __float2half(si[(size_t)k * H + c]);
        th[k][c] = __float2half(sh[(size_t)k * H + c]);
    }
    __syncthreads();
#pragma unroll
    for (int rr = 0; rr < 32; rr += 8) {
        int hr = rr + r0;
        int h  = ht * 32 + hr;
        int np = (h >> 3) * 32 + g * 8 + (h & 7);
        size_t dst = (size_t)l * G4 * H + (size_t)np * H + kt * 32 + c;
        g_wip[dst] = ti[c][hr];
        g_whp[dst] = th[c][hr];
    }
}

__global__ void k_bias(const float* __restrict__ bi, const float* __restrict__ bh) {
    int idx = blockIdx.x * blockDim.x + threadIdx.x;
    if (idx < L * G4) {
        int l = idx / G4, np = idx % G4;
        int jb = np >> 5, g = (np >> 3) & 3, jr = np & 7;
        int h = jb * 8 + jr;
        g_bip[idx] = bi[(l * 4 + g) * H + h];
        g_bhp[idx] = bh[(l * 4 + g) * H + h];
    }
}

__global__ void k_init() {
    int i = blockIdx.x * blockDim.x + threadIdx.x;
    if (i < BH) g_h[i] = __float2half(0.f);   // buffer 0 (zero image == swizzled zero)
    if (i == 0) g_ctr = 0;
}

// ---- input projection GEMM, 3-stage cp.async pipeline + ldmatrix ----
__global__ __launch_bounds__(256) void k_gemm_in(int layer) {
    extern __shared__ __half dsm[];
    const __half* __restrict__ Aseq = (layer == 0) ? g_seqA : g_seqB;
    const __half* __restrict__ Wp   = g_wip + (size_t)layer * G4 * H;
    const float*  __restrict__ bip  = g_bip + layer * G4;

    int tid = threadIdx.x, lane = tid & 31, warp = tid >> 5;
    int wm = warp & 3, wn = warp >> 2;
    int bm = blockIdx.y, bn = blockIdx.x;
    const __half* Ab = Aseq + (size_t)bm * 128 * H;
    const __half* Bb = Wp   + (size_t)bn * 128 * H;

    unsigned sm_u = (unsigned)__cvta_generic_to_shared(dsm);

    auto load_stage = [&](int kti, int s) {
        int kt = kti * 32;
        __half* As = dsm + s * 2 * 128 * 40;
        __half* Bs = As + 128 * 40;
#pragma unroll
        for (int i = 0; i < 2; i++) {
            int idx = i * 256 + tid;
            int r = idx >> 2, c8 = (idx & 3) << 3;
            cpa16(As + r * 40 + c8, &Ab[(size_t)r * H + kt + c8]);
            cpa16(Bs + r * 40 + c8, &Bb[(size_t)r * H + kt + c8]);
        }
        cp_commit();
    };

    float acc[2][8][4];
#pragma unroll
    for (int mt = 0; mt < 2; mt++)
#pragma unroll
        for (int nt = 0; nt < 8; nt++)
#pragma unroll
            for (int i = 0; i < 4; i++) acc[mt][nt][i] = 0.f;

    int a_row    = wm * 32 + (lane & 15);
    int a_coloff = (lane >> 4) * 8;
    int b_row    = wn * 64 + (lane & 7) + ((lane >> 4) & 1) * 8;
    int b_koff   = ((lane >> 3) & 1) * 8;

    load_stage(0, 0);
    load_stage(1, 1);

    for (int kti = 0; kti < 32; kti++) {
        cp_wait<1>();
        __syncthreads();
        if (kti + 2 < 32) load_stage(kti + 2, (kti + 2) % 3);
        else cp_commit();
        unsigned stA = sm_u + (unsigned)((kti % 3) * 2 * 128 * 40) * 2;
        unsigned stB = stA + (unsigned)(128 * 40) * 2;
#pragma unroll
        for (int kk = 0; kk < 2; kk++) {
            unsigned a[2][4], bq[4][4];
            unsigned acol = (unsigned)(kk * 16 + a_coloff) * 2;
            ldm_x4(a[0], stA + (unsigned)(a_row * 40) * 2 + acol);
            ldm_x4(a[1], stA + (unsigned)((a_row + 16) * 40) * 2 + acol);
            unsigned bcol = (unsigned)(kk * 16 + b_koff) * 2;
#pragma unroll
            for (int p = 0; p < 4; p++)
                ldm_x4(bq[p], stB + (unsigned)((b_row + p * 16) * 40) * 2 + bcol);
#pragma unroll
            for (int mt = 0; mt < 2; mt++)
#pragma unroll
                for (int nt = 0; nt < 8; nt++)
                    mma16816(acc[mt][nt], a[mt], &bq[nt >> 1][(nt & 1) * 2]);
        }
    }

#pragma unroll
    for (int mt = 0; mt < 2; mt++)
#pragma unroll
        for (int nt = 0; nt < 8; nt++)
#pragma unroll
            for (int i2 = 0; i2 < 2; i2++) {
                int gr = bm * 128 + wm * 32 + mt * 16 + (lane >> 2) + 8 * i2;
                int gc = bn * 128 + wn * 64 + nt * 8 + (lane & 3) * 2;
                int orow = (layer == 0) ? ((gr & (S - 1)) * B + (gr >> 9)) : gr;
                float2 bv = *(const float2*)&bip[gc];
                float2 v;
                v.x = acc[mt][nt][2 * i2]     + bv.x;
                v.y = acc[mt][nt][2 * i2 + 1] + bv.y;
                *(float2*)&g_gx[(size_t)orow * G4 + gc] = v;
            }
}

// ---- persistent recurrence: bulk-copy h + straight-line MMA + counter barrier ----
// 128 blocks x 128 threads.  Block bx: jb = bx>>1 (64 n'-cols), mh = bx&1 (32 rows).
// h stored in gmem SWIZZLED per 64KB blob: physical colbytes = colbytes ^ ((row&7)<<4).
__global__ __launch_bounds__(128) void k_persist(int layer, float* __restrict__ out) {
    extern __shared__ __half sm[];
    __half (*Whs)[WH_LD] = reinterpret_cast<__half(*)[WH_LD]>(sm);
    char* smc = reinterpret_cast<char*>(sm);
    char* Hs  = smc + 64 * WH_LD * 2;            // 64KB h blob (swizzled image)
    unsigned mbar_u = (unsigned)__cvta_generic_to_shared(smc + 64 * WH_LD * 2 + BLOB);

    int bx = blockIdx.x;
    int jb = bx >> 1, mh = bx & 1;
    int tid = threadIdx.x, lane = tid & 31, warp = tid >> 5;
    int wm = warp & 1, wj = warp >> 1;

    // load Wh slice into smem once
    const __half* __restrict__ Wb = g_whp + (size_t)layer * G4 * H + (size_t)jb * 64 * H;
    for (int idx = tid; idx < 64 * 128; idx += 128) {
        int r = idx >> 7, c8 = (idx & 127) << 3;
        *(uint4*)&Whs[r][c8] = *(const uint4*)&Wb[(size_t)r * H + c8];
    }

    const float* __restrict__ bhr = g_bhp + layer * G4 + jb * 64 + wj * 32;
    float2 bh_g[4];
#pragma unroll
    for (int g = 0; g < 4; g++) bh_g[g] = *(const float2*)&bhr[g * 8 + (lane & 3) * 2];

    float creg[2][2] = {{0.f, 0.f}, {0.f, 0.f}};

    if (tid == 0) {
        mbar_init(mbar_u, 1);
        // REQUIRED: make the mbarrier init visible to the async proxy (TMA)
        // before any cp.async.bulk signals complete_tx on it.  Missing this
        // fence can drop the completion -> infinite mbar_wait spin.
        fence_proxy_async_cta();
    }

    unsigned whs_u = (unsigned)__cvta_generic_to_shared(&Whs[0][0]);
    unsigned hs_u  = (unsigned)__cvta_generic_to_shared(Hs);

    // ldmatrix per-lane constants
    int a_row_loc = wm * 16 + (lane & 15);                    // 0..31, local batch row
    unsigned a_base = hs_u + (unsigned)a_row_loc * 2048;
    unsigned a_xor  = (unsigned)((a_row_loc & 7) << 4);
    unsigned a_coff = (unsigned)((lane >> 4) * 8) * 2;
    int b_n      = wj * 32 + (lane & 7) + ((lane >> 4) & 1) * 8;
    int b_koff   = ((lane >> 3) & 1) * 8;
    unsigned baddr0 = whs_u + (unsigned)(b_n * WH_LD + b_koff) * 2;

    int jbase = jb * 16 + wj * 8 + (lane & 3) * 2;

    __syncthreads();

    for (int t = 0; t < S; t++) {
        // gx prefetch (t-only; latency hides under barrier detection)
        float2 gxp[2][4];
#pragma unroll
        for (int i2 = 0; i2 < 2; i2++) {
            int r = mh * 32 + wm * 16 + (lane >> 2) + 8 * i2;
            const float* gxr = g_gx + ((size_t)t * B + r) * G4 + jb * 64 + wj * 32;
#pragma unroll
            for (int g = 0; g < 4; g++)
                gxp[i2][g] = *(const float2*)&gxr[g * 8 + (lane & 3) * 2];
        }

        // wait until all blocks finished step t-1
        if (warp == 0) {
            unsigned tgt = (unsigned)(NBP * t);
            while (ld_acq(&g_ctr) < tgt) { }
        }
        __syncthreads();

        // one bulk copy: this block's 64KB h blob (already swizzled in gmem)
        if (tid == 0) {
            const char* src = (const char*)g_h + (size_t)(t & 1) * (BH * 2) + mh * BLOB;
            mbar_expect_tx(mbar_u, BLOB);
            bulk_g2s(hs_u, src, BLOB, mbar_u);
        }
        mbar_wait(mbar_u, (unsigned)(t & 1));

        // straight-line GEMM: no internal barriers
        float acc[4][4];
#pragma unroll
        for (int nt = 0; nt < 4; nt++)
#pragma unroll
            for (int i = 0; i < 4; i++) acc[nt][i] = 0.f;

#pragma unroll 4
        for (int kti = 0; kti < 16; kti++) {
#pragma unroll
            for (int kk = 0; kk < 4; kk++) {
                unsigned colb = (unsigned)((kti * 64 + kk * 16) * 2);
                unsigned a[4], bq0[4], bq1[4];
                ldm_x4(a, a_base + ((colb + a_coff) ^ a_xor));
                ldm_x4(bq0, baddr0 + colb);                               // gates 0,1
                ldm_x4(bq1, baddr0 + (unsigned)(16 * WH_LD) * 2 + colb);  // gates 2,3
                mma16816(acc[0], a, &bq0[0]);
                mma16816(acc[1], a, &bq0[2]);
                mma16816(acc[2], a, &bq1[0]);
                mma16816(acc[3], a, &bq1[2]);
            }
        }

        // elementwise LSTM update; all 4 gates of an output are in this lane
        float hv_a[2][2], cn_a[2][2];
        char* houtb = (char*)g_h + (size_t)((t + 1) & 1) * (BH * 2);
#pragma unroll
        for (int i2 = 0; i2 < 2; i2++) {
            int r = mh * 32 + wm * 16 + (lane >> 2) + 8 * i2;    // batch index
#pragma unroll
            for (int bs = 0; bs < 2; bs++) {
                int ai = 2 * i2 + bs;
                float pi = acc[0][ai] + (bs ? gxp[i2][0].y : gxp[i2][0].x) + (bs ? bh_g[0].y : bh_g[0].x);
                float pf = acc[1][ai] + (bs ? gxp[i2][1].y : gxp[i2][1].x) + (bs ? bh_g[1].y : bh_g[1].x);
                float pg = acc[2][ai] + (bs ? gxp[i2][2].y : gxp[i2][2].x) + (bs ? bh_g[2].y : bh_g[2].x);
                float po = acc[3][ai] + (bs ? gxp[i2][3].y : gxp[i2][3].x) + (bs ? bh_g[3].y : bh_g[3].x);
                float ig = 1.f / (1.f + __expf(-pi));
                float fg = 1.f / (1.f + __expf(-pf));
                float gg = tanhf(pg);
                float og = 1.f / (1.f + __expf(-po));
                float cn = fg * creg[i2][bs] + ig * gg;
                creg[i2][bs] = cn;
                cn_a[i2][bs] = cn;
                hv_a[i2][bs] = og * tanhf(cn);
            }
            // swizzled h store: blob = r>>5, row-local = r&31
            int rloc = r & 31;
            char* dst = houtb + (r >> 5) * BLOB + rloc * 2048
                        + (((unsigned)(jbase * 2)) ^ ((unsigned)((rloc & 7) << 4)));
            *(__half2*)dst = __floats2half2_rn(hv_a[i2][0], hv_a[i2][1]);
        }

        // publish: all h stores done (ordered by bar.sync) -> release arrival
        __syncthreads();
        if (tid == 0) {
            __threadfence();
            atom_add_release(&g_ctr, 1u);
        }

        // remaining stores overlap other blocks' detection
#pragma unroll
        for (int i2 = 0; i2 < 2; i2++) {
            int r = mh * 32 + wm * 16 + (lane >> 2) + 8 * i2;
            if (layer == 0)
                *(__half2*)&g_seqB[((size_t)t * B + r) * H + jbase] =
                    __floats2half2_rn(hv_a[i2][0], hv_a[i2][1]);
            if (t == S - 1) {
#pragma unroll
                for (int bs = 0; bs < 2; bs++) {
                    int j = jbase + bs;
                    out[BH + layer * BH + r * H + j]          = hv_a[i2][bs];  // h_n[l]
                    out[BH + L * BH + layer * BH + r * H + j] = cn_a[i2][bs];  // c_n[l]
                    if (layer == L - 1) out[r * H + j] = hv_a[i2][bs];         // seq[:,-1,:]
                }
            }
        }
    }
}

extern "C" void kernel_launch(void* const* d_in, const int* in_sizes, int n_in,
                              void* d_out, int out_size) {
    (void)in_sizes; (void)n_in; (void)out_size;
    const float* x  = (const float*)d_in[0];
    const float* Wi = (const float*)d_in[1];
    const float* bi = (const float*)d_in[2];
    const float* Wh = (const float*)d_in[3];
    const float* bh = (const float*)d_in[4];
    float* out = (float*)d_out;

    cudaFuncSetAttribute(k_persist, cudaFuncAttributeMaxDynamicSharedMemorySize, SMEM_PERSIST);
    cudaFuncSetAttribute(k_gemm_in, cudaFuncAttributeMaxDynamicSharedMemorySize, SMEM_GEMM);

    k_convert_x<<<(BSH / 4 + 255) / 256, 256>>>((const float4*)x);
    k_transpose_w<<<L * 4 * 32 * 32, 256>>>(Wi, Wh);
    k_bias<<<(L * G4 + 255) / 256, 256>>>(bi, bh);

    for (int l = 0; l < L; l++) {
        dim3 grid(G4 / 128, (B * S) / 128);   // (32, 256)
        k_gemm_in<<<grid, 256, SMEM_GEMM>>>(l);
        k_init<<<(BH + 255) / 256, 256>>>();
        k_persist<<<NBP, 128, SMEM_PERSIST>>>(l, out);
    }
}